// round 15
// baseline (speedup 1.0000x reference)
#include <cuda_runtime.h>
#include <math.h>

#define NK 10
#define NIMG 8    // 0..2 = A channels, 3..7 = packed kernel pairs

// ---------------- scratch (static device globals; no allocation) ----------------
__device__ __align__(16) float2 g_cA[NIMG * 65536];
__device__ __align__(16) float2 g_cB[NIMG * 65536];
__device__ __align__(16) float2 g_gr[5 * 65536];   // growth pairs (gr_2j, gr_2j+1)
__device__ float2 g_tw256[256];         // [n1*16+k2] = exp(-2*pi*i*n1*k2/256)
__device__ float  g_Asum[256][256];
__device__ double g_part[NK][256];
__device__ double g_ksum[NK];
__device__ __align__(16) float g_mu[256*256*6];

__constant__ int c_pairA[5]  = {0,0,1,2,2};   // C0[2j]
__constant__ int c_pairB[5]  = {0,1,1,2,0};   // C0[2j+1]

// W16^j = exp(-2*pi*i*j/16), j = 0..9
__constant__ float2 c_w16[10] = {
    { 1.0f, 0.0f},
    { 0.92387953251128674f, -0.38268343236508977f},
    { 0.70710678118654752f, -0.70710678118654752f},
    { 0.38268343236508977f, -0.92387953251128674f},
    { 0.0f, -1.0f},
    {-0.38268343236508977f, -0.92387953251128674f},
    {-0.70710678118654752f, -0.70710678118654752f},
    {-0.92387953251128674f, -0.38268343236508977f},
    {-1.0f, 0.0f},
    {-0.92387953251128674f,  0.38268343236508977f}
};

__device__ __forceinline__ float2 cadd(float2 a, float2 b){ return make_float2(a.x+b.x, a.y+b.y); }
__device__ __forceinline__ float2 csub(float2 a, float2 b){ return make_float2(a.x-b.x, a.y-b.y); }
__device__ __forceinline__ float2 cmul(float2 a, float2 b){
    return make_float2(a.x*b.x - a.y*b.y, a.x*b.y + a.y*b.x);
}

__device__ __forceinline__ void dft4(float2 a, float2 b, float2 c, float2 d,
                                     float2& o0, float2& o1, float2& o2, float2& o3) {
    float2 t0 = cadd(a, c), t1 = csub(a, c);
    float2 t2 = cadd(b, d);
    float2 bd = csub(b, d);
    float2 t3 = make_float2(bd.y, -bd.x);     // -i*(b-d)
    o0 = cadd(t0, t2);
    o1 = cadd(t1, t3);
    o2 = csub(t0, t2);
    o3 = csub(t1, t3);
}

// 16-pt FFT, natural order in/out, fully in registers (4x4 four-step).
__device__ __forceinline__ void fft16(float2 v[16]) {
    float2 y[16];
    // step 1: DFT4 over n2 (x[n1 + 4 n2]) for each n1; y[k2*4 + n1] = Y[n1][k2]
    #pragma unroll
    for (int n1 = 0; n1 < 4; n1++) {
        dft4(v[n1], v[n1+4], v[n1+8], v[n1+12],
             y[n1], y[n1+4], y[n1+8], y[n1+12]);
    }
    // step 2: twiddle W16^{n1*k2}
    #pragma unroll
    for (int k2 = 1; k2 < 4; k2++) {
        #pragma unroll
        for (int n1 = 1; n1 < 4; n1++) {
            y[k2*4 + n1] = cmul(y[k2*4 + n1], c_w16[n1*k2]);
        }
    }
    // step 3: DFT4 over n1 for each k2; out[k2 + 4*k1]
    #pragma unroll
    for (int k2 = 0; k2 < 4; k2++) {
        dft4(y[k2*4+0], y[k2*4+1], y[k2*4+2], y[k2*4+3],
             v[k2], v[k2+4], v[k2+8], v[k2+12]);
    }
}

// ---------------- kernel-profile value ----------------
__device__ __forceinline__ float kval(float D, float invS,
                                      const float* a, const float* b, const float* w, int k) {
    float Dk = D * invS;
    float val = 0.0f;
    if (Dk < 2.9f) {   // reference's fp32 tanh saturates -> sig exactly 0 past ~2.81
        float ker = 0.0f;
        #pragma unroll
        for (int t = 0; t < 3; t++) {
            float d = Dk - a[k*3+t];
            ker += b[k*3+t] * __expf(-__fdividef(d*d, w[k*3+t]));
        }
        float sig = __fdividef(1.0f, 1.0f + __expf((Dk - 1.0f) * 10.0f));
        val = sig * ker;
    }
    return val;
}

// ---------------- 1. init: prep rows (blk<256) + quadrant kbuild (blk>=256) ------
__global__ void __launch_bounds__(256) init_kernel(
    const float* __restrict__ A,
    const float* __restrict__ R,
    const float* __restrict__ r,
    const float* __restrict__ a,
    const float* __restrict__ b,
    const float* __restrict__ w)
{
    __shared__ double sd[256];
    int blk = blockIdx.x, tid = threadIdx.x;

    if (blk < 256) {                 // ---- prep ----
        int x = blk, y = tid;
        float a0 = A[(x*256+y)*3+0];
        float a1 = A[(x*256+y)*3+1];
        float a2 = A[(x*256+y)*3+2];
        g_Asum[x][y] = a0 + a1 + a2;
        int idx = x*256 + y;
        g_cA[0*65536 + idx] = make_float2(a0, 0.f);
        g_cA[1*65536 + idx] = make_float2(a1, 0.f);
        g_cA[2*65536 + idx] = make_float2(a2, 0.f);
        if (x == 0) {
            int n1 = y >> 4, k2 = y & 15;
            double ang = -2.0 * M_PI * (double)(n1 * k2) / 256.0;
            g_tw256[y] = make_float2((float)cos(ang), (float)sin(ang));
        }
        return;
    }

    // ---- kbuild: one quadrant, mirrored 4x ----
    int job = blk - 256;             // 0..644
    int p = job / 129;               // kernel pair 0..4
    int i = job - p*129;             // |dx| = 0..128
    int j = tid;                     // |dy| (active j<=128)
    int k0 = 2*p, k1 = 2*p + 1;
    int im = (256 - i) & 255;
    int jm = (256 - j) & 255;

    float v0 = 0.f, v1 = 0.f;
    if (j <= 128) {
        float D = sqrtf((float)(i*i + j*j));
        float Rv = R[0] + 15.0f;
        v0 = kval(D, __fdividef(1.0f, Rv * r[k0]), a, b, w, k0);
        v1 = kval(D, __fdividef(1.0f, Rv * r[k1]), a, b, w, k1);
        float2 kp = make_float2(v0, v1);
        float2* base = g_cA + (3+p)*65536;
        base[i*256 + j] = kp;
        if (jm != j) base[i*256 + jm] = kp;
        if (im != i) {
            base[im*256 + j] = kp;
            if (jm != j) base[im*256 + jm] = kp;
        }
    }

    double wgt = (j >= 1 && j <= 127) ? 2.0 : ((j <= 128) ? 1.0 : 0.0);
    sd[tid] = wgt * (double)v0;
    __syncthreads();
    for (int st = 128; st > 0; st >>= 1) {
        if (tid < st) sd[tid] += sd[tid + st];
        __syncthreads();
    }
    if (tid == 0) {
        g_part[k0][i] = sd[0];
        if (im != i) g_part[k0][im] = sd[0];
    }
    __syncthreads();
    sd[tid] = wgt * (double)v1;
    __syncthreads();
    for (int st = 128; st > 0; st >>= 1) {
        if (tid < st) sd[tid] += sd[tid + st];
        __syncthreads();
    }
    if (tid == 0) {
        g_part[k1][i] = sd[0];
        if (im != i) g_part[k1][im] = sd[0];
    }
}

// ---------------- 2. 256-pt FFT pass via 16x16 four-step (register FFT-16) -------
// 16 threads per transform, 8 transforms per 128-thread block.
// MODE 0: g_cA -> g_cB (forward pass 1; block NIMG*32 computes ksum)
// MODE 1: g_cB -> g_cA (forward pass 2)
// MODE 2: fused multiply+conj: read spectra from g_cA, FFT, -> g_cB (inverse pass 1)
// MODE 3: inverse pass 2 + fused growth: g_cB -> g_gr
// Every pass stores transposed (dst[q*256 + row]); two passes restore natural order.
template <int MODE>
__global__ void __launch_bounds__(128) fft16_pass(
    const float* __restrict__ m,
    const float* __restrict__ s,
    const float* __restrict__ h)
{
    __shared__ float2 sm[8][16][17];
    __shared__ double sd[128];
    int tid = threadIdx.x;
    int blk = blockIdx.x;

    if (MODE == 0 && blk >= NIMG*32) {   // ---- ksum (deterministic) ----
        for (int k = 0; k < NK; k++) {
            sd[tid] = g_part[k][tid] + g_part[k][tid + 128];
            __syncthreads();
            for (int st = 64; st > 0; st >>= 1) {
                if (tid < st) sd[tid] += sd[tid + st];
                __syncthreads();
            }
            if (tid == 0) g_ksum[k] = sd[0];
            __syncthreads();
        }
        return;
    }

    int u = tid >> 4;                  // transform within block (0..7)
    int t = tid & 15;                  // thread within transform (= n1)
    int img = blk >> 5;
    int row = (blk & 31) * 8 + u;

    float2 v[16];
    if (MODE == 2) {
        // conj(Q), Q = fK_a*fA_a + i*fK_b*fA_b ; fK_a = Re(Kpack), fK_b = Im(Kpack)
        const float2* Kp = g_cA + (3+img)*65536 + row*256;
        const float2* Fa = g_cA + c_pairA[img]*65536 + row*256;
        const float2* Fb = g_cA + c_pairB[img]*65536 + row*256;
        #pragma unroll
        for (int n2 = 0; n2 < 16; n2++) {
            int q = t + 16*n2;
            float2 kp = Kp[q];
            float2 fa = Fa[q];
            float2 fb = Fb[q];
            v[n2] = make_float2(kp.x*fa.x - kp.y*fb.y, -(kp.x*fa.y) - kp.y*fb.x);
        }
    } else {
        const float2* src = (MODE == 0 ? g_cA : g_cB) + img*65536 + row*256;
        #pragma unroll
        for (int n2 = 0; n2 < 16; n2++) v[n2] = src[t + 16*n2];
    }

    // step A: FFT over n2 -> Y[t][k2], then twiddle W256^{t*k2}
    fft16(v);
    const float2* tw = g_tw256 + t*16;
    #pragma unroll
    for (int k2 = 1; k2 < 16; k2++) v[k2] = cmul(v[k2], tw[k2]);

    // exchange: transpose 16x16 within the transform
    #pragma unroll
    for (int k2 = 0; k2 < 16; k2++) sm[u][t][k2] = v[k2];
    __syncthreads();
    float2 wv[16];
    #pragma unroll
    for (int n1 = 0; n1 < 16; n1++) wv[n1] = sm[u][n1][t];

    // step B: FFT over n1 -> X[t + 16*k1] = wv[k1]
    fft16(wv);

    if (MODE == 3) {
        // fused growth: z = (U_2j, -U_2j+1) * 65536 * ksum  ->  store gr pair
        int k0 = 2*img, k1i = k0 + 1;
        float invk0 = (float)(1.0 / (65536.0 * g_ksum[k0]));
        float invk1 = (float)(1.0 / (65536.0 * g_ksum[k1i]));
        float m0 = m[k0], m1 = m[k1i];
        float is0 = __fdividef(1.0f, s[k0]), is1 = __fdividef(1.0f, s[k1i]);
        float h0 = h[k0], h1 = h[k1i];
        float2* dst = g_gr + img*65536;
        #pragma unroll
        for (int k1 = 0; k1 < 16; k1++) {
            float2 z = wv[k1];
            float U0 = z.x * invk0;
            float U1 = -z.y * invk1;
            float gg0 = (U0 - m0) * is0;
            float gg1 = (U1 - m1) * is1;
            float g0 = (__expf(-0.5f * gg0 * gg0) * 2.0f - 1.0f) * h0;
            float g1 = (__expf(-0.5f * gg1 * gg1) * 2.0f - 1.0f) * h1;
            dst[(t + 16*k1)*256 + row] = make_float2(g0, g1);
        }
    } else {
        float2* dst = (MODE == 1 ? g_cA : g_cB) + img*65536;
        #pragma unroll
        for (int k1 = 0; k1 < 16; k1++) {
            dst[(t + 16*k1)*256 + row] = wv[k1];
        }
    }
}

// ---------------- 3. fused combine+sobel+mu (16x16 tile, halo 1) ----------------
__device__ __forceinline__ float padv(const float* p, int xx, int yy) {
    return (xx >= 0 && xx < 256 && yy >= 0 && yy < 256) ? p[xx*256 + yy] : 0.0f;
}

__global__ void __launch_bounds__(256) musolve_kernel(const float* __restrict__ A)
{
    __shared__ float s_u[18*18*3];
    int tid = threadIdx.x, bx = blockIdx.x;
    int X0 = (bx >> 4) * 16, Y0 = (bx & 15) * 16;

    // channel-group sums of precomputed growth over the 18x18 halo tile
    for (int e = tid; e < 18*18; e += 256) {
        int ii = e / 18, jj = e - ii*18;
        int gx = X0 - 1 + ii, gy = Y0 - 1 + jj;
        float u0 = 0.f, u1 = 0.f, u2 = 0.f;
        if (gx >= 0 && gx < 256 && gy >= 0 && gy < 256) {
            int idx = gx*256 + gy;
            float2 z0 = g_gr[0*65536 + idx];   // gr0(grp0), gr1(grp0)
            float2 z1 = g_gr[1*65536 + idx];   // gr2(grp0), gr3(grp1)
            float2 z2 = g_gr[2*65536 + idx];   // gr4(grp1), gr5(grp1)
            float2 z3 = g_gr[3*65536 + idx];   // gr6(grp2), gr7(grp2)
            float2 z4 = g_gr[4*65536 + idx];   // gr8(grp2), gr9(grp0)
            u0 = z0.x + z0.y + z1.x + z4.y;
            u1 = z1.y + z2.x + z2.y;
            u2 = z3.x + z3.y + z4.x;
        }
        s_u[e*3+0] = u0; s_u[e*3+1] = u1; s_u[e*3+2] = u2;
    }
    __syncthreads();

    int lx = tid >> 4, ly = tid & 15;
    int x = X0 + lx, y = Y0 + ly;
    const float* As = &g_Asum[0][0];
    float nA0 = (padv(As,x-1,y-1) + 2.0f*padv(As,x-1,y) + padv(As,x-1,y+1))
              - (padv(As,x+1,y-1) + 2.0f*padv(As,x+1,y) + padv(As,x+1,y+1));
    float nA1 = (padv(As,x-1,y-1) + 2.0f*padv(As,x,y-1) + padv(As,x+1,y-1))
              - (padv(As,x-1,y+1) + 2.0f*padv(As,x,y+1) + padv(As,x+1,y+1));

    float px = (float)x + 0.5f;
    float py = (float)y + 0.5f;
    #pragma unroll
    for (int c = 0; c < 3; c++) {
        #define SU(ii,jj) s_u[(((ii))*18 + (jj))*3 + c]
        float nU0 = (SU(lx,ly)   + 2.0f*SU(lx,ly+1)   + SU(lx,ly+2))
                  - (SU(lx+2,ly) + 2.0f*SU(lx+2,ly+1) + SU(lx+2,ly+2));
        float nU1 = (SU(lx,ly)   + 2.0f*SU(lx+1,ly)   + SU(lx+2,ly))
                  - (SU(lx,ly+2) + 2.0f*SU(lx+1,ly+2) + SU(lx+2,ly+2));
        #undef SU
        float Ac = A[(x*256+y)*3 + c];
        float al = Ac * (1.0f/3.0f);
        al = al * al;
        al = fminf(al, 1.0f);
        float F0 = nU0 * (1.0f - al) - nA0 * al;
        float F1 = nU1 * (1.0f - al) - nA1 * al;
        float d0 = fminf(fmaxf(0.2f * F0, -4.35f), 4.35f);
        float d1 = fminf(fmaxf(0.2f * F1, -4.35f), 4.35f);
        float mux = fminf(fmaxf(px + d0, 0.65f), 255.35f);
        float muy = fminf(fmaxf(py + d1, 0.65f), 255.35f);
        g_mu[(x*256+y)*6 + c*2 + 0] = mux;
        g_mu[(x*256+y)*6 + c*2 + 1] = muy;
    }
}

// ---------------- 4. reintegration tracking (smem-tiled gather) ----------------
__global__ void __launch_bounds__(256) gather_kernel(const float* __restrict__ A,
                                                     float* __restrict__ out) {
    __shared__ float s_mu[26*26*6];
    __shared__ float s_a[26*26*3];
    int tid = threadIdx.x;
    int tx = tid & 15;
    int ty = tid >> 4;
    int X0 = blockIdx.x * 16, Y0 = blockIdx.y * 16;

    for (int idx = tid; idx < 26*26; idx += 256) {
        int ii = idx / 26, jj = idx - ii*26;
        int gi = (X0 - 5 + ii) & 255;
        int gj = (Y0 - 5 + jj) & 255;
        const float2* mu = (const float2*)(g_mu + (gi*256 + gj)*6);
        float2* d = (float2*)(s_mu + idx*6);
        d[0] = mu[0]; d[1] = mu[1]; d[2] = mu[2];
        s_a[idx*3+0] = A[(gi*256+gj)*3+0];
        s_a[idx*3+1] = A[(gi*256+gj)*3+1];
        s_a[idx*3+2] = A[(gi*256+gj)*3+2];
    }
    __syncthreads();

    int x = X0 + ty, y = Y0 + tx;
    float px = (float)x + 0.5f;
    float py = (float)y + 0.5f;
    float acc0 = 0.0f, acc1 = 0.0f, acc2 = 0.0f;
    const float inv = 1.0f / 1.69f;   // 1/(4*sigma^2)

    #pragma unroll
    for (int dx = -5; dx <= 5; ++dx) {
        int si = ty + 5 - dx;
        #pragma unroll
        for (int dy = -5; dy <= 5; ++dy) {
            int sj = tx + 5 - dy;
            int base = si*26 + sj;
            const float* mu = s_mu + base*6;
            const float* av = s_a + base*3;
            #pragma unroll
            for (int c = 0; c < 3; c++) {
                float ax = 1.15f - fabsf(px - mu[2*c + 0]);
                float ay = 1.15f - fabsf(py - mu[2*c + 1]);
                ax = fminf(fmaxf(ax, 0.0f), 1.0f);
                ay = fminf(fmaxf(ay, 0.0f), 1.0f);
                float area = ax * ay * inv;
                if (c == 0) acc0 = fmaf(av[0], area, acc0);
                else if (c == 1) acc1 = fmaf(av[1], area, acc1);
                else acc2 = fmaf(av[2], area, acc2);
            }
        }
    }
    out[(x*256+y)*3 + 0] = acc0;
    out[(x*256+y)*3 + 1] = acc1;
    out[(x*256+y)*3 + 2] = acc2;
}

// ---------------- launch ----------------
extern "C" void kernel_launch(void* const* d_in, const int* in_sizes, int n_in,
                              void* d_out, int out_size) {
    const float* A = (const float*)d_in[0];
    const float* R = (const float*)d_in[1];
    const float* r = (const float*)d_in[2];
    const float* m = (const float*)d_in[3];
    const float* s = (const float*)d_in[4];
    const float* h = (const float*)d_in[5];
    const float* a = (const float*)d_in[6];
    const float* b = (const float*)d_in[7];
    const float* w = (const float*)d_in[8];
    float* out = (float*)d_out;

    init_kernel<<<256 + 5*129, 256>>>(A, R, r, a, b, w);
    // forward 2D FFT of 8 images (two transposing passes); extra block of pass 1 = ksum
    fft16_pass<0><<<NIMG*32 + 1, 128>>>(m, s, h);
    fft16_pass<1><<<NIMG*32, 128>>>(m, s, h);
    // inverse of 5 packed products (mult+conj fused into pass 1, growth into pass 2)
    fft16_pass<2><<<5*32, 128>>>(m, s, h);
    fft16_pass<3><<<5*32, 128>>>(m, s, h);
    musolve_kernel<<<256, 256>>>(A);
    gather_kernel<<<dim3(16, 16), 256>>>(A, out);
}

// round 16
// speedup vs baseline: 1.0684x; 1.0684x over previous
#include <cuda_runtime.h>
#include <math.h>

#define NK 10
#define NIMG 8    // 0..2 = A channels, 3..7 = packed kernel pairs

// ---------------- scratch (static device globals; no allocation) ----------------
__device__ __align__(16) float2 g_cA[NIMG * 65536];
__device__ __align__(16) float2 g_cB[NIMG * 65536];
__device__ __align__(16) float2 g_gr[5 * 65536];   // growth pairs (gr_2j, gr_2j+1)
__device__ float2 g_tw[128];            // tw[Ns+k] = exp(-i*pi*k/(2*Ns)), Ns in {1,4,16,64}
__device__ float  g_Asum[256][256];
__device__ double g_part[NK][256];
__device__ double g_ksum[NK];

__constant__ int c_pairA[5]  = {0,0,1,2,2};   // C0[2j]
__constant__ int c_pairB[5]  = {0,1,1,2,0};   // C0[2j+1]

__device__ __forceinline__ float2 cadd(float2 a, float2 b){ return make_float2(a.x+b.x, a.y+b.y); }
__device__ __forceinline__ float2 csub(float2 a, float2 b){ return make_float2(a.x-b.x, a.y-b.y); }
__device__ __forceinline__ float2 cmul(float2 a, float2 b){
    return make_float2(a.x*b.x - a.y*b.y, a.x*b.y + a.y*b.x);
}

// ---------------- kernel-profile value ----------------
__device__ __forceinline__ float kval(float D, float invS,
                                      const float* a, const float* b, const float* w, int k) {
    float Dk = D * invS;
    float val = 0.0f;
    if (Dk < 2.9f) {   // reference's fp32 tanh saturates -> sig exactly 0 past ~2.81
        float ker = 0.0f;
        #pragma unroll
        for (int t = 0; t < 3; t++) {
            float d = Dk - a[k*3+t];
            ker += b[k*3+t] * __expf(-__fdividef(d*d, w[k*3+t]));
        }
        float sig = __fdividef(1.0f, 1.0f + __expf((Dk - 1.0f) * 10.0f));
        val = sig * ker;
    }
    return val;
}

// ---------------- 1. init: prep rows (blk<256) + quadrant kbuild (blk>=256) ------
__global__ void __launch_bounds__(256) init_kernel(
    const float* __restrict__ A,
    const float* __restrict__ R,
    const float* __restrict__ r,
    const float* __restrict__ a,
    const float* __restrict__ b,
    const float* __restrict__ w)
{
    __shared__ double sd[256];
    int blk = blockIdx.x, tid = threadIdx.x;

    if (blk < 256) {                 // ---- prep ----
        int x = blk, y = tid;
        float a0 = A[(x*256+y)*3+0];
        float a1 = A[(x*256+y)*3+1];
        float a2 = A[(x*256+y)*3+2];
        g_Asum[x][y] = a0 + a1 + a2;
        int idx = x*256 + y;
        g_cA[0*65536 + idx] = make_float2(a0, 0.f);
        g_cA[1*65536 + idx] = make_float2(a1, 0.f);
        g_cA[2*65536 + idx] = make_float2(a2, 0.f);
        if (x == 0 && y < 128) {
            if (y == 0) {
                g_tw[0] = make_float2(1.f, 0.f);
            } else {
                int pp = 31 - __clz(y);
                int Ns = 1 << pp;
                int kk = y - Ns;
                double ang = -M_PI * (double)kk / (2.0 * (double)Ns);
                g_tw[y] = make_float2((float)cos(ang), (float)sin(ang));
            }
        }
        return;
    }

    // ---- kbuild: one quadrant, mirrored 4x ----
    int job = blk - 256;             // 0..644
    int p = job / 129;               // kernel pair 0..4
    int i = job - p*129;             // |dx| = 0..128
    int j = tid;                     // |dy| (active j<=128)
    int k0 = 2*p, k1 = 2*p + 1;
    int im = (256 - i) & 255;
    int jm = (256 - j) & 255;

    float v0 = 0.f, v1 = 0.f;
    if (j <= 128) {
        float D = sqrtf((float)(i*i + j*j));
        float Rv = R[0] + 15.0f;
        v0 = kval(D, __fdividef(1.0f, Rv * r[k0]), a, b, w, k0);
        v1 = kval(D, __fdividef(1.0f, Rv * r[k1]), a, b, w, k1);
        float2 kp = make_float2(v0, v1);
        float2* base = g_cA + (3+p)*65536;
        base[i*256 + j] = kp;
        if (jm != j) base[i*256 + jm] = kp;
        if (im != i) {
            base[im*256 + j] = kp;
            if (jm != j) base[im*256 + jm] = kp;
        }
    }

    double wgt = (j >= 1 && j <= 127) ? 2.0 : ((j <= 128) ? 1.0 : 0.0);
    sd[tid] = wgt * (double)v0;
    __syncthreads();
    for (int st = 128; st > 0; st >>= 1) {
        if (tid < st) sd[tid] += sd[tid + st];
        __syncthreads();
    }
    if (tid == 0) {
        g_part[k0][i] = sd[0];
        if (im != i) g_part[k0][im] = sd[0];
    }
    __syncthreads();
    sd[tid] = wgt * (double)v1;
    __syncthreads();
    for (int st = 128; st > 0; st >>= 1) {
        if (tid < st) sd[tid] += sd[tid + st];
        __syncthreads();
    }
    if (tid == 0) {
        g_part[k1][i] = sd[0];
        if (im != i) g_part[k1][im] = sd[0];
    }
}

// ---------------- 2. radix-4 Stockham 256-pt FFT pass, 2 rows/block --------------
// MODE 0: g_cA -> g_cB (forward pass 1; extra block (>=8*128) computes ksum)
// MODE 1: g_cB -> g_cA (forward pass 2)
// MODE 2: fused multiply+conj: read spectra from g_cA, FFT, -> g_cB (inverse pass 1)
// MODE 3: inverse pass 2 + fused growth: g_cB -> g_gr
// Every pass writes transposed; two passes restore natural order.
template <int MODE>
__global__ void __launch_bounds__(128) fft2_pass(
    const float* __restrict__ m,
    const float* __restrict__ s,
    const float* __restrict__ h)
{
    __shared__ float2 sb[2][2][258];
    __shared__ double sd[128];
    int tid = threadIdx.x;
    int blk = blockIdx.x;

    if (MODE == 0 && blk >= NIMG*128) {   // ---- ksum (deterministic) ----
        for (int k = 0; k < NK; k++) {
            sd[tid] = g_part[k][tid] + g_part[k][tid + 128];
            __syncthreads();
            for (int st = 64; st > 0; st >>= 1) {
                if (tid < st) sd[tid] += sd[tid + st];
                __syncthreads();
            }
            if (tid == 0) g_ksum[k] = sd[0];
            __syncthreads();
        }
        return;
    }

    int tx = tid & 63;
    int ty = tid >> 6;                 // 0..1
    int img = blk >> 7;
    int rb  = (blk & 127) * 2;
    int row = rb + ty;
    float2* B0 = sb[0][ty];

    if (MODE == 2) {
        // conj(Q), Q = fK_a*fA_a + i*fK_b*fA_b ; fK_a = Re(Kpack), fK_b = Im(Kpack)
        const float2* Kp = g_cA + (3+img)*65536 + row*256;
        const float2* Fa = g_cA + c_pairA[img]*65536 + row*256;
        const float2* Fb = g_cA + c_pairB[img]*65536 + row*256;
        #pragma unroll
        for (int i = 0; i < 4; i++) {
            int q = tx + i*64;
            float2 kp = Kp[q];
            float2 fa = Fa[q];
            float2 fb = Fb[q];
            B0[q] = make_float2(kp.x*fa.x - kp.y*fb.y, -(kp.x*fa.y) - kp.y*fb.x);
        }
    } else {
        const float2* src = (MODE == 0 ? g_cA : g_cB) + img*65536 + row*256;
        #pragma unroll
        for (int i = 0; i < 4; i++) B0[tx + i*64] = src[tx + i*64];
    }
    __syncthreads();

    #pragma unroll
    for (int p = 0; p < 4; p++) {
        float2* X = sb[p & 1][ty];
        float2* Y = sb[(p + 1) & 1][ty];
        int Ns = 1 << (2*p);
        int kk = tx & (Ns - 1);
        float2 av = X[tx];
        float2 bv = X[tx + 64];
        float2 cv = X[tx + 128];
        float2 dv = X[tx + 192];
        if (p > 0) {                   // stage 0 twiddles are all 1
            float2 w1 = g_tw[Ns + kk];
            float2 w2 = cmul(w1, w1);
            float2 w3 = cmul(w2, w1);
            bv = cmul(bv, w1); cv = cmul(cv, w2); dv = cmul(dv, w3);
        }
        float2 t0 = cadd(av, cv), t1 = csub(av, cv), t2 = cadd(bv, dv);
        float2 bd = csub(bv, dv);
        float2 t3 = make_float2(bd.y, -bd.x);      // -i*(b-d)
        int o = ((tx >> (2*p)) << (2*p + 2)) + kk;
        Y[o]        = cadd(t0, t2);
        Y[o + Ns]   = cadd(t1, t3);
        Y[o + 2*Ns] = csub(t0, t2);
        Y[o + 3*Ns] = csub(t1, t3);
        __syncthreads();
    }

    if (MODE == 3) {
        // fused growth: z = (U_2j, -U_2j+1) * 65536 * ksum  ->  store gr pair
        int k0 = 2*img, k1 = k0 + 1;
        float invk0 = (float)(1.0 / (65536.0 * g_ksum[k0]));
        float invk1 = (float)(1.0 / (65536.0 * g_ksum[k1]));
        float m0 = m[k0], m1 = m[k1];
        float is0 = __fdividef(1.0f, s[k0]), is1 = __fdividef(1.0f, s[k1]);
        float h0 = h[k0], h1 = h[k1];
        float2* dst = g_gr + img*65536;
        #pragma unroll
        for (int i = 0; i < 4; i++) {
            int e = tid + i*128;
            int q = e >> 1, rr = e & 1;
            float2 z = sb[0][rr][q];
            float U0 = z.x * invk0;
            float U1 = -z.y * invk1;
            float gg0 = (U0 - m0) * is0;
            float gg1 = (U1 - m1) * is1;
            float g0 = (__expf(-0.5f * gg0 * gg0) * 2.0f - 1.0f) * h0;
            float g1 = (__expf(-0.5f * gg1 * gg1) * 2.0f - 1.0f) * h1;
            dst[q*256 + rb + rr] = make_float2(g0, g1);
        }
    } else {
        float2* dst = (MODE == 1 ? g_cA : g_cB) + img*65536;
        #pragma unroll
        for (int i = 0; i < 4; i++) {
            int e = tid + i*128;
            int q = e >> 1, rr = e & 1;
            dst[q*256 + rb + rr] = sb[0][rr][q];
        }
    }
}

// ---------------- 3. fused combine+sobel+mu+gather (16x16 output tile) -----------
// Stages: (1) 28x28 halo of channel-group growth sums + Asum into smem,
//         (2) mu for the 26x26 gather halo (sobel with seam masks = zero padding
//             in TRUE coordinates, matching the reference's 'same' conv),
//         (3) reintegration-tracking gather.
__global__ void __launch_bounds__(256) gather_kernel(const float* __restrict__ A,
                                                     float* __restrict__ out) {
    __shared__ float s_u[28*28*3];
    __shared__ float s_as[28*28];
    __shared__ float s_mu[26*26*6];
    __shared__ float s_a[26*26*3];
    int tid = threadIdx.x;
    int X0 = blockIdx.x * 16, Y0 = blockIdx.y * 16;

    // ---- stage 1: load halos ----
    for (int e = tid; e < 28*28; e += 256) {
        int iu = e / 28, ju = e - iu*28;
        int gi = (X0 - 6 + iu) & 255;
        int gj = (Y0 - 6 + ju) & 255;
        int idx = gi*256 + gj;
        float2 z0 = g_gr[0*65536 + idx];   // gr0(grp0), gr1(grp0)
        float2 z1 = g_gr[1*65536 + idx];   // gr2(grp0), gr3(grp1)
        float2 z2 = g_gr[2*65536 + idx];   // gr4(grp1), gr5(grp1)
        float2 z3 = g_gr[3*65536 + idx];   // gr6(grp2), gr7(grp2)
        float2 z4 = g_gr[4*65536 + idx];   // gr8(grp2), gr9(grp0)
        s_u[e*3+0] = z0.x + z0.y + z1.x + z4.y;
        s_u[e*3+1] = z1.y + z2.x + z2.y;
        s_u[e*3+2] = z3.x + z3.y + z4.x;
        s_as[e] = g_Asum[gi][gj];
    }
    for (int e = tid; e < 26*26; e += 256) {
        int ii = e / 26, jj = e - ii*26;
        int gi = (X0 - 5 + ii) & 255;
        int gj = (Y0 - 5 + jj) & 255;
        s_a[e*3+0] = A[(gi*256+gj)*3+0];
        s_a[e*3+1] = A[(gi*256+gj)*3+1];
        s_a[e*3+2] = A[(gi*256+gj)*3+2];
    }
    __syncthreads();

    // ---- stage 2: mu for all 26x26 cells ----
    for (int e = tid; e < 26*26; e += 256) {
        int ii = e / 26, jj = e - ii*26;
        int iu = ii + 1, ju = jj + 1;
        int gi = (X0 - 5 + ii) & 255;
        int gj = (Y0 - 5 + jj) & 255;
        // seam masks: neighbor in TRUE coords is out of grid -> contributes 0
        float vxm = (gi == 0)   ? 0.f : 1.f;
        float vxp = (gi == 255) ? 0.f : 1.f;
        float vym = (gj == 0)   ? 0.f : 1.f;
        float vyp = (gj == 255) ? 0.f : 1.f;

        #define CELL(arr, di, dj) arr[((iu+(di))*28 + (ju+(dj)))]
        float amm = CELL(s_as,-1,-1)*vxm*vym, am0 = CELL(s_as,-1,0)*vxm, amp = CELL(s_as,-1,1)*vxm*vyp;
        float a0m = CELL(s_as, 0,-1)*vym,                                a0p = CELL(s_as, 0,1)*vyp;
        float apm = CELL(s_as, 1,-1)*vxp*vym, ap0 = CELL(s_as, 1,0)*vxp, app = CELL(s_as, 1,1)*vxp*vyp;
        #undef CELL
        float nA0 = (amm + 2.0f*am0 + amp) - (apm + 2.0f*ap0 + app);
        float nA1 = (amm + 2.0f*a0m + apm) - (amp + 2.0f*a0p + app);

        float px = (float)gi + 0.5f;
        float py = (float)gj + 0.5f;
        #pragma unroll
        for (int c = 0; c < 3; c++) {
            #define UC(di, dj) s_u[(((iu+(di))*28 + (ju+(dj))))*3 + c]
            float umm = UC(-1,-1)*vxm*vym, um0 = UC(-1,0)*vxm, ump = UC(-1,1)*vxm*vyp;
            float u0m = UC(0,-1)*vym,                          u0p = UC(0,1)*vyp;
            float upm = UC(1,-1)*vxp*vym,  up0 = UC(1,0)*vxp,  upp = UC(1,1)*vxp*vyp;
            #undef UC
            float nU0 = (umm + 2.0f*um0 + ump) - (upm + 2.0f*up0 + upp);
            float nU1 = (umm + 2.0f*u0m + upm) - (ump + 2.0f*u0p + upp);
            float Ac = s_a[e*3 + c];
            float al = Ac * (1.0f/3.0f);
            al = al * al;
            al = fminf(al, 1.0f);
            float F0 = nU0 * (1.0f - al) - nA0 * al;
            float F1 = nU1 * (1.0f - al) - nA1 * al;
            float d0 = fminf(fmaxf(0.2f * F0, -4.35f), 4.35f);
            float d1 = fminf(fmaxf(0.2f * F1, -4.35f), 4.35f);
            s_mu[e*6 + c*2 + 0] = fminf(fmaxf(px + d0, 0.65f), 255.35f);
            s_mu[e*6 + c*2 + 1] = fminf(fmaxf(py + d1, 0.65f), 255.35f);
        }
    }
    __syncthreads();

    // ---- stage 3: gather ----
    int tx = tid & 15;
    int ty = tid >> 4;
    int x = X0 + ty, y = Y0 + tx;
    float px = (float)x + 0.5f;
    float py = (float)y + 0.5f;
    float acc0 = 0.0f, acc1 = 0.0f, acc2 = 0.0f;
    const float inv = 1.0f / 1.69f;   // 1/(4*sigma^2)

    #pragma unroll
    for (int dx = -5; dx <= 5; ++dx) {
        int si = ty + 5 - dx;
        #pragma unroll
        for (int dy = -5; dy <= 5; ++dy) {
            int sj = tx + 5 - dy;
            int base = si*26 + sj;
            const float* mu = s_mu + base*6;
            const float* av = s_a + base*3;
            #pragma unroll
            for (int c = 0; c < 3; c++) {
                float ax = 1.15f - fabsf(px - mu[2*c + 0]);
                float ay = 1.15f - fabsf(py - mu[2*c + 1]);
                ax = fminf(fmaxf(ax, 0.0f), 1.0f);
                ay = fminf(fmaxf(ay, 0.0f), 1.0f);
                float area = ax * ay * inv;
                if (c == 0) acc0 = fmaf(av[0], area, acc0);
                else if (c == 1) acc1 = fmaf(av[1], area, acc1);
                else acc2 = fmaf(av[2], area, acc2);
            }
        }
    }
    out[(x*256+y)*3 + 0] = acc0;
    out[(x*256+y)*3 + 1] = acc1;
    out[(x*256+y)*3 + 2] = acc2;
}

// ---------------- launch ----------------
extern "C" void kernel_launch(void* const* d_in, const int* in_sizes, int n_in,
                              void* d_out, int out_size) {
    const float* A = (const float*)d_in[0];
    const float* R = (const float*)d_in[1];
    const float* r = (const float*)d_in[2];
    const float* m = (const float*)d_in[3];
    const float* s = (const float*)d_in[4];
    const float* h = (const float*)d_in[5];
    const float* a = (const float*)d_in[6];
    const float* b = (const float*)d_in[7];
    const float* w = (const float*)d_in[8];
    float* out = (float*)d_out;

    init_kernel<<<256 + 5*129, 256>>>(A, R, r, a, b, w);
    // forward 2D FFT of 8 images (two transposing passes); extra block of pass 1 = ksum
    fft2_pass<0><<<NIMG*128 + 1, 128>>>(m, s, h);
    fft2_pass<1><<<NIMG*128, 128>>>(m, s, h);
    // inverse of 5 packed products (mult+conj fused into pass 1, growth into pass 2)
    fft2_pass<2><<<5*128, 128>>>(m, s, h);
    fft2_pass<3><<<5*128, 128>>>(m, s, h);
    gather_kernel<<<dim3(16, 16), 256>>>(A, out);
}

// round 17
// speedup vs baseline: 1.2309x; 1.1521x over previous
#include <cuda_runtime.h>
#include <math.h>

#define NK 10
#define NIMG 8    // 0..2 = A channels, 3..7 = packed kernel pairs

// ---------------- scratch (static device globals; no allocation) ----------------
__device__ __align__(16) float2 g_cA[NIMG * 65536];   // spectra (fwd2 output)
__device__ __align__(16) float2 g_cB[NIMG * 65536];   // fwd1 / inv1 output
__device__ __align__(16) float2 g_gr[5 * 65536];      // growth pairs (gr_2j, gr_2j+1)
__device__ double g_part[NK][256];
__device__ double g_ksum[NK];

__constant__ int c_pairA[5]  = {0,0,1,2,2};   // C0[2j]
__constant__ int c_pairB[5]  = {0,1,1,2,0};   // C0[2j+1]

__device__ __forceinline__ float2 cadd(float2 a, float2 b){ return make_float2(a.x+b.x, a.y+b.y); }
__device__ __forceinline__ float2 csub(float2 a, float2 b){ return make_float2(a.x-b.x, a.y-b.y); }
__device__ __forceinline__ float2 cmul(float2 a, float2 b){
    return make_float2(a.x*b.x - a.y*b.y, a.x*b.y + a.y*b.x);
}

// per-block twiddle table: s_tw[Ns+k] = exp(-i*pi*k/(2*Ns)), Ns in {1,4,16,64}
__device__ __forceinline__ void build_tw(float2* s_tw, int tid) {
    if (tid < 128) {
        if (tid == 0) {
            s_tw[0] = make_float2(1.f, 0.f);
        } else {
            int pp = 31 - __clz(tid);
            int Ns = 1 << pp;
            int kk = tid - Ns;
            float ang = -1.57079632679489662f * (float)kk / (float)Ns;
            float sv, cv;
            sincosf(ang, &sv, &cv);
            s_tw[tid] = make_float2(cv, sv);
        }
    }
}

// radix-4 Stockham 256-pt FFT, 64 threads/transform, result ends in b0.
__device__ __forceinline__ void fft256(float2* b0, float2* b1, int t, const float2* s_tw) {
    #pragma unroll
    for (int p = 0; p < 4; p++) {
        float2* X = (p & 1) ? b1 : b0;
        float2* Y = (p & 1) ? b0 : b1;
        int Ns = 1 << (2*p);
        int kk = t & (Ns - 1);
        float2 av = X[t];
        float2 bv = X[t + 64];
        float2 cv = X[t + 128];
        float2 dv = X[t + 192];
        if (p > 0) {                   // stage 0 twiddles are all 1
            float2 w1 = s_tw[Ns + kk];
            float2 w2 = cmul(w1, w1);
            float2 w3 = cmul(w2, w1);
            bv = cmul(bv, w1); cv = cmul(cv, w2); dv = cmul(dv, w3);
        }
        float2 t0 = cadd(av, cv), t1 = csub(av, cv), t2 = cadd(bv, dv);
        float2 bd = csub(bv, dv);
        float2 t3 = make_float2(bd.y, -bd.x);      // -i*(b-d)
        int o = ((t >> (2*p)) << (2*p + 2)) + kk;
        Y[o]        = cadd(t0, t2);
        Y[o + Ns]   = cadd(t1, t3);
        Y[o + 2*Ns] = csub(t0, t2);
        Y[o + 3*Ns] = csub(t1, t3);
        __syncthreads();
    }
}

// ---------------- kernel-profile value ----------------
__device__ __forceinline__ float kval(float D, float invS,
                                      const float* a, const float* b, const float* w, int k) {
    float Dk = D * invS;
    float val = 0.0f;
    if (Dk < 2.9f) {   // reference's fp32 tanh saturates -> sig exactly 0 past ~2.81
        float ker = 0.0f;
        #pragma unroll
        for (int t = 0; t < 3; t++) {
            float d = Dk - a[k*3+t];
            ker += b[k*3+t] * __expf(-__fdividef(d*d, w[k*3+t]));
        }
        float sig = __fdividef(1.0f, 1.0f + __expf((Dk - 1.0f) * 10.0f));
        val = sig * ker;
    }
    return val;
}

// ---------------- 1. forward FFT pass 1, producers fused ----------------
// blk < 384: A images (img = blk>>7), rows read directly from input A.
// blk >= 384: K pair images. Each block COMPUTES its 2 kernel rows (rows 0..128
// only — K is x-symmetric so spectra of rows r and 256-r are identical and both
// get written), accumulates double row sums into g_part, then FFTs.
__global__ void __launch_bounds__(128) fwd1_kernel(
    const float* __restrict__ A,
    const float* __restrict__ R,
    const float* __restrict__ r,
    const float* __restrict__ a,
    const float* __restrict__ b,
    const float* __restrict__ w)
{
    __shared__ float2 sb[2][2][258];
    __shared__ float2 s_tw[128];
    __shared__ double sd[2][64];
    int tid = threadIdx.x, blk = blockIdx.x;
    int ty = tid >> 6, t = tid & 63;

    build_tw(s_tw, tid);

    if (blk < 384) {                      // ---- A images ----
        int img = blk >> 7;
        int rb = (blk & 127) * 2;
        int row = rb + ty;
        float2* B0 = sb[0][ty];
        #pragma unroll
        for (int i = 0; i < 4; i++) {
            int j = t + i*64;
            B0[j] = make_float2(A[(row*256 + j)*3 + img], 0.f);
        }
        __syncthreads();
        fft256(sb[0][ty], sb[1][ty], t, s_tw);
        float2* dst = g_cB + img*65536;
        #pragma unroll
        for (int i = 0; i < 4; i++) {
            int e = tid + i*128;
            int q = e >> 1, rr = e & 1;
            dst[q*256 + rb + rr] = sb[0][rr][q];
        }
    } else {                              // ---- K pair images ----
        int job = blk - 384;              // 0..324
        int p  = job / 65;                // pair 0..4
        int bb = job - p*65;              // 0..64
        int rb = bb * 2;
        int row = min(rb + ty, 128);      // block 64: both groups do row 128
        int k0 = 2*p, k1 = k0 + 1;
        float Rv = R[0] + 15.0f;
        float invS0 = __fdividef(1.0f, Rv * r[k0]);
        float invS1 = __fdividef(1.0f, Rv * r[k1]);
        float2* B0 = sb[0][ty];
        float frow2 = (float)(row * row);
        #pragma unroll
        for (int i = 0; i < 2; i++) {
            int j = t + i*64;             // 0..127
            float D = sqrtf(frow2 + (float)(j*j));
            float2 kp = make_float2(kval(D, invS0, a, b, w, k0),
                                    kval(D, invS1, a, b, w, k1));
            B0[j] = kp;
            if (j >= 1) B0[256 - j] = kp; // y-mirror
        }
        if (t == 0) {
            float D = sqrtf(frow2 + 16384.0f);
            B0[128] = make_float2(kval(D, invS0, a, b, w, k0),
                                  kval(D, invS1, a, b, w, k1));
        }
        __syncthreads();

        // deterministic double row sums for both packed components
        int mi = (256 - row) & 255;
        double sx = 0.0, sy = 0.0;
        #pragma unroll
        for (int i = 0; i < 4; i++) {
            float2 v = B0[t + i*64];
            sx += (double)v.x;
            sy += (double)v.y;
        }
        sd[ty][t] = sx;
        __syncthreads();
        for (int st = 32; st > 0; st >>= 1) {
            if (t < st) sd[ty][t] += sd[ty][t + st];
            __syncthreads();
        }
        if (t == 0) {
            g_part[k0][row] = sd[ty][0];
            if (mi != row) g_part[k0][mi] = sd[ty][0];
        }
        __syncthreads();
        sd[ty][t] = sy;
        __syncthreads();
        for (int st = 32; st > 0; st >>= 1) {
            if (t < st) sd[ty][t] += sd[ty][t + st];
            __syncthreads();
        }
        if (t == 0) {
            g_part[k1][row] = sd[ty][0];
            if (mi != row) g_part[k1][mi] = sd[ty][0];
        }
        __syncthreads();

        fft256(sb[0][ty], sb[1][ty], t, s_tw);

        float2* dst = g_cB + (3 + p)*65536;
        #pragma unroll
        for (int i = 0; i < 4; i++) {
            int e = tid + i*128;
            int q = e >> 1, rr = e & 1;
            int ri = rb + rr;
            if (ri <= 128) {
                float2 v = sb[0][rr][q];
                dst[q*256 + ri] = v;
                int mr = (256 - ri) & 255;
                if (mr != ri) dst[q*256 + mr] = v;   // x-mirror row: same spectrum
            }
        }
    }
}

// ---------------- 2. FFT passes 2..4 (radix-4 Stockham, 2 rows/block) -----------
// MODE 1: g_cB -> g_cA (forward pass 2; extra block >= NIMG*128 computes ksum)
// MODE 2: fused multiply+conj: read spectra from g_cA, FFT, -> g_cB (inverse pass 1)
// MODE 3: inverse pass 2 + fused growth: g_cB -> g_gr
template <int MODE>
__global__ void __launch_bounds__(128) fft2_pass(
    const float* __restrict__ m,
    const float* __restrict__ s,
    const float* __restrict__ h)
{
    __shared__ float2 sb[2][2][258];
    __shared__ float2 s_tw[128];
    __shared__ double sd[128];
    int tid = threadIdx.x;
    int blk = blockIdx.x;

    if (MODE == 1 && blk >= NIMG*128) {   // ---- ksum (deterministic) ----
        for (int k = 0; k < NK; k++) {
            sd[tid] = g_part[k][tid] + g_part[k][tid + 128];
            __syncthreads();
            for (int st = 64; st > 0; st >>= 1) {
                if (tid < st) sd[tid] += sd[tid + st];
                __syncthreads();
            }
            if (tid == 0) g_ksum[k] = sd[0];
            __syncthreads();
        }
        return;
    }

    build_tw(s_tw, tid);

    int tx = tid & 63;
    int ty = tid >> 6;                 // 0..1
    int img = blk >> 7;
    int rb  = (blk & 127) * 2;
    int row = rb + ty;
    float2* B0 = sb[0][ty];

    if (MODE == 2) {
        // conj(Q), Q = fK_a*fA_a + i*fK_b*fA_b ; fK_a = Re(Kpack), fK_b = Im(Kpack)
        const float2* Kp = g_cA + (3+img)*65536 + row*256;
        const float2* Fa = g_cA + c_pairA[img]*65536 + row*256;
        const float2* Fb = g_cA + c_pairB[img]*65536 + row*256;
        #pragma unroll
        for (int i = 0; i < 4; i++) {
            int q = tx + i*64;
            float2 kp = Kp[q];
            float2 fa = Fa[q];
            float2 fb = Fb[q];
            B0[q] = make_float2(kp.x*fa.x - kp.y*fb.y, -(kp.x*fa.y) - kp.y*fb.x);
        }
    } else {
        const float2* src = (MODE == 1 ? g_cB : g_cB) + img*65536 + row*256;
        #pragma unroll
        for (int i = 0; i < 4; i++) B0[tx + i*64] = src[tx + i*64];
    }
    __syncthreads();

    fft256(sb[0][ty], sb[1][ty], tx, s_tw);

    if (MODE == 3) {
        // fused growth: z = (U_2j, -U_2j+1) * 65536 * ksum  ->  store gr pair
        int k0 = 2*img, k1 = k0 + 1;
        float invk0 = (float)(1.0 / (65536.0 * g_ksum[k0]));
        float invk1 = (float)(1.0 / (65536.0 * g_ksum[k1]));
        float m0 = m[k0], m1 = m[k1];
        float is0 = __fdividef(1.0f, s[k0]), is1 = __fdividef(1.0f, s[k1]);
        float h0 = h[k0], h1 = h[k1];
        float2* dst = g_gr + img*65536;
        #pragma unroll
        for (int i = 0; i < 4; i++) {
            int e = tid + i*128;
            int q = e >> 1, rr = e & 1;
            float2 z = sb[0][rr][q];
            float U0 = z.x * invk0;
            float U1 = -z.y * invk1;
            float gg0 = (U0 - m0) * is0;
            float gg1 = (U1 - m1) * is1;
            float g0 = (__expf(-0.5f * gg0 * gg0) * 2.0f - 1.0f) * h0;
            float g1 = (__expf(-0.5f * gg1 * gg1) * 2.0f - 1.0f) * h1;
            dst[q*256 + rb + rr] = make_float2(g0, g1);
        }
    } else {
        float2* dst = (MODE == 1 ? g_cA : g_cB) + img*65536;
        #pragma unroll
        for (int i = 0; i < 4; i++) {
            int e = tid + i*128;
            int q = e >> 1, rr = e & 1;
            dst[q*256 + rb + rr] = sb[0][rr][q];
        }
    }
}

// ---------------- 3. fused Asum+combine+sobel+mu+gather (16x16 output tile) ------
__global__ void __launch_bounds__(256) gather_kernel(const float* __restrict__ A,
                                                     float* __restrict__ out) {
    __shared__ float  s_a28[28*28*3];
    __shared__ float  s_as[28*28];
    __shared__ float  s_u[28*28*3];
    __shared__ float4 s_p1[26*26];   // (mu0x, mu0y, mu1x, mu1y)
    __shared__ float4 s_p2[26*26];   // (mu2x, mu2y, av0, av1)
    __shared__ float  s_v2[26*26];   // av2
    int tid = threadIdx.x;
    int X0 = blockIdx.x * 16, Y0 = blockIdx.y * 16;

    // ---- stage 1: load A halo (derive Asum) + growth channel-group sums ----
    for (int e = tid; e < 28*28; e += 256) {
        int iu = e / 28, ju = e - iu*28;
        int gi = (X0 - 6 + iu) & 255;
        int gj = (Y0 - 6 + ju) & 255;
        int idx = gi*256 + gj;
        float a0 = A[idx*3+0], a1 = A[idx*3+1], a2 = A[idx*3+2];
        s_a28[e*3+0] = a0; s_a28[e*3+1] = a1; s_a28[e*3+2] = a2;
        s_as[e] = a0 + a1 + a2;
        float2 z0 = g_gr[0*65536 + idx];   // gr0(grp0), gr1(grp0)
        float2 z1 = g_gr[1*65536 + idx];   // gr2(grp0), gr3(grp1)
        float2 z2 = g_gr[2*65536 + idx];   // gr4(grp1), gr5(grp1)
        float2 z3 = g_gr[3*65536 + idx];   // gr6(grp2), gr7(grp2)
        float2 z4 = g_gr[4*65536 + idx];   // gr8(grp2), gr9(grp0)
        s_u[e*3+0] = z0.x + z0.y + z1.x + z4.y;
        s_u[e*3+1] = z1.y + z2.x + z2.y;
        s_u[e*3+2] = z3.x + z3.y + z4.x;
    }
    __syncthreads();

    // ---- stage 2: mu for all 26x26 cells (seam masks = zero pad in TRUE coords) --
    for (int e = tid; e < 26*26; e += 256) {
        int ii = e / 26, jj = e - ii*26;
        int iu = ii + 1, ju = jj + 1;
        int gi = (X0 - 5 + ii) & 255;
        int gj = (Y0 - 5 + jj) & 255;
        float vxm = (gi == 0)   ? 0.f : 1.f;
        float vxp = (gi == 255) ? 0.f : 1.f;
        float vym = (gj == 0)   ? 0.f : 1.f;
        float vyp = (gj == 255) ? 0.f : 1.f;

        #define CELL(arr, di, dj) arr[((iu+(di))*28 + (ju+(dj)))]
        float amm = CELL(s_as,-1,-1)*vxm*vym, am0 = CELL(s_as,-1,0)*vxm, amp = CELL(s_as,-1,1)*vxm*vyp;
        float a0m = CELL(s_as, 0,-1)*vym,                                a0p = CELL(s_as, 0,1)*vyp;
        float apm = CELL(s_as, 1,-1)*vxp*vym, ap0 = CELL(s_as, 1,0)*vxp, app = CELL(s_as, 1,1)*vxp*vyp;
        #undef CELL
        float nA0 = (amm + 2.0f*am0 + amp) - (apm + 2.0f*ap0 + app);
        float nA1 = (amm + 2.0f*a0m + apm) - (amp + 2.0f*a0p + app);

        int ci = (iu*28 + ju)*3;
        float av0 = s_a28[ci+0], av1 = s_a28[ci+1], av2 = s_a28[ci+2];
        float avc[3] = {av0, av1, av2};
        float mux[3], muy[3];
        float px = (float)gi + 0.5f;
        float py = (float)gj + 0.5f;
        #pragma unroll
        for (int c = 0; c < 3; c++) {
            #define UC(di, dj) s_u[(((iu+(di))*28 + (ju+(dj))))*3 + c]
            float umm = UC(-1,-1)*vxm*vym, um0 = UC(-1,0)*vxm, ump = UC(-1,1)*vxm*vyp;
            float u0m = UC(0,-1)*vym,                          u0p = UC(0,1)*vyp;
            float upm = UC(1,-1)*vxp*vym,  up0 = UC(1,0)*vxp,  upp = UC(1,1)*vxp*vyp;
            #undef UC
            float nU0 = (umm + 2.0f*um0 + ump) - (upm + 2.0f*up0 + upp);
            float nU1 = (umm + 2.0f*u0m + upm) - (ump + 2.0f*u0p + upp);
            float al = avc[c] * (1.0f/3.0f);
            al = al * al;
            al = fminf(al, 1.0f);
            float F0 = nU0 * (1.0f - al) - nA0 * al;
            float F1 = nU1 * (1.0f - al) - nA1 * al;
            float d0 = fminf(fmaxf(0.2f * F0, -4.35f), 4.35f);
            float d1 = fminf(fmaxf(0.2f * F1, -4.35f), 4.35f);
            mux[c] = fminf(fmaxf(px + d0, 0.65f), 255.35f);
            muy[c] = fminf(fmaxf(py + d1, 0.65f), 255.35f);
        }
        s_p1[e] = make_float4(mux[0], muy[0], mux[1], muy[1]);
        s_p2[e] = make_float4(mux[2], muy[2], av0, av1);
        s_v2[e] = av2;
    }
    __syncthreads();

    // ---- stage 3: reintegration gather (vectorized smem reads) ----
    int tx = tid & 15;
    int ty = tid >> 4;
    int x = X0 + ty, y = Y0 + tx;
    float px = (float)x + 0.5f;
    float py = (float)y + 0.5f;
    float acc0 = 0.0f, acc1 = 0.0f, acc2 = 0.0f;
    const float inv = 1.0f / 1.69f;   // 1/(4*sigma^2)

    #pragma unroll
    for (int dx = -5; dx <= 5; ++dx) {
        int si = ty + 5 - dx;
        #pragma unroll
        for (int dy = -5; dy <= 5; ++dy) {
            int sj = tx + 5 - dy;
            int base = si*26 + sj;
            float4 p1 = s_p1[base];
            float4 p2 = s_p2[base];
            float  v2 = s_v2[base];
            float ax, ay;
            ax = fminf(fmaxf(1.15f - fabsf(px - p1.x), 0.0f), 1.0f);
            ay = fminf(fmaxf(1.15f - fabsf(py - p1.y), 0.0f), 1.0f);
            acc0 = fmaf(p2.z, ax * ay * inv, acc0);
            ax = fminf(fmaxf(1.15f - fabsf(px - p1.z), 0.0f), 1.0f);
            ay = fminf(fmaxf(1.15f - fabsf(py - p1.w), 0.0f), 1.0f);
            acc1 = fmaf(p2.w, ax * ay * inv, acc1);
            ax = fminf(fmaxf(1.15f - fabsf(px - p2.x), 0.0f), 1.0f);
            ay = fminf(fmaxf(1.15f - fabsf(py - p2.y), 0.0f), 1.0f);
            acc2 = fmaf(v2, ax * ay * inv, acc2);
        }
    }
    out[(x*256+y)*3 + 0] = acc0;
    out[(x*256+y)*3 + 1] = acc1;
    out[(x*256+y)*3 + 2] = acc2;
}

// ---------------- launch ----------------
extern "C" void kernel_launch(void* const* d_in, const int* in_sizes, int n_in,
                              void* d_out, int out_size) {
    const float* A = (const float*)d_in[0];
    const float* R = (const float*)d_in[1];
    const float* r = (const float*)d_in[2];
    const float* m = (const float*)d_in[3];
    const float* s = (const float*)d_in[4];
    const float* h = (const float*)d_in[5];
    const float* a = (const float*)d_in[6];
    const float* b = (const float*)d_in[7];
    const float* w = (const float*)d_in[8];
    float* out = (float*)d_out;

    // fwd pass 1 with fused producers: 3 A imgs (128 blocks each) + 5 K imgs (65 each)
    fwd1_kernel<<<3*128 + 5*65, 128>>>(A, R, r, a, b, w);
    // fwd pass 2 (8 imgs) + ksum extra block
    fft2_pass<1><<<NIMG*128 + 1, 128>>>(m, s, h);
    // inverse of 5 packed products (mult+conj fused into pass 1, growth into pass 2)
    fft2_pass<2><<<5*128, 128>>>(m, s, h);
    fft2_pass<3><<<5*128, 128>>>(m, s, h);
    gather_kernel<<<dim3(16, 16), 256>>>(A, out);
}